// round 4
// baseline (speedup 1.0000x reference)
#include <cuda_runtime.h>

typedef unsigned long long u64;

#define NB 1024
#define SL 512
#define NL 64

__device__ __forceinline__ u64 fma2(u64 a, u64 b, u64 c) {
    u64 d;
    asm("fma.rn.f32x2 %0, %1, %2, %3;" : "=l"(d) : "l"(a), "l"(b), "l"(c));
    return d;
}
__device__ __forceinline__ u64 add2(u64 a, u64 b) {
    u64 d;
    asm("add.rn.f32x2 %0, %1, %2;" : "=l"(d) : "l"(a), "l"(b));
    return d;
}
__device__ __forceinline__ u64 pack2(float lo, float hi) {
    u64 d;
    asm("mov.b64 %0, {%1, %2};" : "=l"(d) : "f"(lo), "f"(hi));
    return d;
}
__device__ __forceinline__ void unpack2(u64 a, float& lo, float& hi) {
    asm("mov.b64 {%0, %1}, %2;" : "=f"(lo), "=f"(hi) : "l"(a));
}

// One 64-thread block = one batch element. Thread j owns column j and computes
// the FULL matvec for it (16 LDS.128 broadcast + 32 fma2, 4 chains x depth 8).
// ONE __syncthreads per step (double-buffered q).
//
// Multiplicative recurrence (no MUFU on the critical path):
//   s_j = sum_i q_i * E_ij            (E = exp(transitions), in registers)
//   q'_j = s_j * exp(em_j - C_t)      (cf computed at step top, hidden)
//   Z   += C_t
// C_t = ln q_0^{t-1} + em_0^t is a scalar published one step in advance by
// thread 0; its __logf runs after the STS, off the serial chain.
// mask=0: q, Z, d all unchanged.
__global__ __launch_bounds__(64) void crf_fwd_kernel(
    const float* __restrict__ emissions,
    const int*   __restrict__ mask,
    const float* __restrict__ trans,
    const float* __restrict__ startt,
    const float* __restrict__ endt,
    float* __restrict__ out)
{
    __shared__ __align__(16) float qbuf[2][NL];
    __shared__ float csm[2];
    __shared__ float red[2];

    const int tid = threadIdx.x;
    const int w   = tid >> 5;
    const int l   = tid & 31;
    const int b   = blockIdx.x;
    const size_t ebase = (size_t)b * SL * NL;
    const int j = tid;                    // owned column

    // E column j, packed over adjacent row pairs matching q's smem layout.
    u64 E[32];
#pragma unroll
    for (int m = 0; m < 32; m++) {
        E[m] = pack2(__expf(trans[(2 * m) * NL + j]),
                     __expf(trans[(2 * m + 1) * NL + j]));
    }
    const float fend = __expf(endt[j]);

    // t = 0: score = start + em0, normalized by score_0 (broadcast via smem).
    float sc = startt[j] + emissions[ebase + j];
    if (tid == 0) red[0] = sc;
    __syncthreads();
    const float z0 = red[0];
    float q = __expf(sc - z0);
    float Z = z0;
    float d = 0.0f;                       // ln q_0 (thread 0 only)
    qbuf[0][j] = q;

    // prefetch t = 1
    float em_n = emissions[ebase + NL + j];
    int   mk_n = mask[b * SL + 1];
    if (tid == 0) csm[0] = d + em_n;      // C_1 = ln q_0^0 + em_0^1

#pragma unroll 2
    for (int t = 1; t < SL; t++) {
        __syncthreads();                  // publishes qbuf[pb], csm[pb]
        const int pb  = (t - 1) & 1;
        const int cbf = t & 1;
        const float C  = csm[pb];
        const float em = em_n;
        const int   mk = mk_n;

        int tn = t + 1; if (tn >= SL) tn = SL - 1;
        em_n = emissions[ebase + (size_t)tn * NL + j];
        mk_n = mask[b * SL + tn];

        // hidden under the LDS + FMA tree
        const float cf = __expf(em - C);

        // full matvec: s_j = sum_i q_i * E_ij
        const ulonglong2* qp = (const ulonglong2*)qbuf[pb];
        u64 a0 = 0, a1 = 0, a2 = 0, a3 = 0;
#pragma unroll
        for (int k = 0; k < 8; k++) {
            ulonglong2 v0 = qp[2 * k];
            ulonglong2 v1 = qp[2 * k + 1];
            a0 = fma2(v0.x, E[4 * k + 0], a0);
            a1 = fma2(v0.y, E[4 * k + 1], a1);
            a2 = fma2(v1.x, E[4 * k + 2], a2);
            a3 = fma2(v1.y, E[4 * k + 3], a3);
        }
        float sx, sy;
        unpack2(add2(add2(a0, a1), add2(a2, a3)), sx, sy);
        const float s = sx + sy;

        if (mk) { q = s * cf; Z += C; }
        qbuf[cbf][j] = q;                  // STS immediately — shortest chain

        if (tid == 0) {                    // off the critical path
            if (mk) d = __logf(s) + (em - C);   // ln q_0^t
            csm[cbf] = d + em_n;                // C_{t+1}
        }
    }

    // out[b] = Z + ln( sum_j q_j * exp(end_j) )
    float v = q * fend;
#pragma unroll
    for (int o = 16; o; o >>= 1) v += __shfl_xor_sync(0xffffffffu, v, o);
    if (l == 0) red[w] = v;
    __syncthreads();
    if (tid == 0) out[b] = Z + __logf(red[0] + red[1]);
}

extern "C" void kernel_launch(void* const* d_in, const int* in_sizes, int n_in,
                              void* d_out, int out_size) {
    const float* emissions = (const float*)d_in[0];
    const int*   msk       = (const int*)d_in[1];
    const float* trans     = (const float*)d_in[2];
    const float* startt    = (const float*)d_in[3];
    const float* endt      = (const float*)d_in[4];
    crf_fwd_kernel<<<NB, NL>>>(emissions, msk, trans, startt, endt, (float*)d_out);
}

// round 5
// speedup vs baseline: 1.0289x; 1.0289x over previous
#include <cuda_runtime.h>

typedef unsigned long long u64;

#define NB 1024
#define SL 512
#define NL 64

__device__ __forceinline__ u64 fma2(u64 a, u64 b, u64 c) {
    u64 d;
    asm("fma.rn.f32x2 %0, %1, %2, %3;" : "=l"(d) : "l"(a), "l"(b), "l"(c));
    return d;
}
__device__ __forceinline__ u64 add2(u64 a, u64 b) {
    u64 d;
    asm("add.rn.f32x2 %0, %1, %2;" : "=l"(d) : "l"(a), "l"(b));
    return d;
}
__device__ __forceinline__ u64 pack2(float lo, float hi) {
    u64 d;
    asm("mov.b64 %0, {%1, %2};" : "=l"(d) : "f"(lo), "f"(hi));
    return d;
}
__device__ __forceinline__ void unpack2(u64 a, float& lo, float& hi) {
    asm("mov.b64 {%0, %1}, %2;" : "=f"(lo), "=f"(hi) : "l"(a));
}

// One 64-thread block = one batch. Thread j owns column j (full matvec:
// 16 LDS.128 broadcast + 32 fma2). ONE __syncthreads per step.
//
// Multiplicative recurrence, EXACT for any scalar normalizer C:
//   s_j = sum_i q_i E_ij ;  q'_j = s_j * exp(em_j - C) ;  Z += C
// C_{t+1} = em_0^{t+1} + n*ln2, n = ilogb(q_0^t): 3 ALU ops for thread 0
// (predicated, no branch, NO log anywhere in the hot loop). n*ln2 tracks
// ln q_0 within 0.7, keeping all exponents comfortably inside fp32 range.
__global__ __launch_bounds__(64) void crf_fwd_kernel(
    const float* __restrict__ emissions,
    const int*   __restrict__ mask,
    const float* __restrict__ trans,
    const float* __restrict__ startt,
    const float* __restrict__ endt,
    float* __restrict__ out)
{
    __shared__ __align__(16) float qbuf[2][NL];
    __shared__ float csm[2];
    __shared__ float red[2];

    const int tid = threadIdx.x;
    const int w   = tid >> 5;
    const int l   = tid & 31;
    const int b   = blockIdx.x;
    const size_t ebase = (size_t)b * SL * NL;
    const int j = tid;

    // E column j, packed over adjacent row pairs (matches q smem layout).
    u64 E[32];
#pragma unroll
    for (int m = 0; m < 32; m++) {
        E[m] = pack2(__expf(trans[(2 * m) * NL + j]),
                     __expf(trans[(2 * m + 1) * NL + j]));
    }
    const float fend = __expf(endt[j]);
    const float LN2 = 0.6931471805599453f;

    // t = 0: normalize by score_0 -> q_0 = 1 exactly.
    float sc = startt[j] + emissions[ebase + j];
    if (tid == 0) red[0] = sc;
    __syncthreads();
    const float z0 = red[0];
    float q = __expf(sc - z0);
    float Z = z0;
    qbuf[0][j] = q;

    // prefetch t = 1
    float em_n = emissions[ebase + NL + j];
    int   mk_n = mask[b * SL + 1];
    if (tid == 0) csm[0] = em_n;          // C_1 = em_0^1 + 0*ln2 (q_0 = 1)

#pragma unroll 2
    for (int t = 1; t < SL; t++) {
        __syncthreads();                  // publishes qbuf[pb], csm[pb]
        const int pb  = (t - 1) & 1;
        const int cbf = t & 1;
        const float C  = csm[pb];
        const float em = em_n;
        const int   mk = mk_n;

        int tn = t + 1; if (tn >= SL) tn = SL - 1;
        em_n = emissions[ebase + (size_t)tn * NL + j];
        mk_n = mask[b * SL + tn];

        // hidden under the LDS + FMA tree
        const float cf = __expf(em - C);

        // full matvec: s_j = sum_i q_i * E_ij
        const ulonglong2* qp = (const ulonglong2*)qbuf[pb];
        u64 a0 = 0, a1 = 0, a2 = 0, a3 = 0;
#pragma unroll
        for (int k = 0; k < 8; k++) {
            ulonglong2 v0 = qp[2 * k];
            ulonglong2 v1 = qp[2 * k + 1];
            a0 = fma2(v0.x, E[4 * k + 0], a0);
            a1 = fma2(v0.y, E[4 * k + 1], a1);
            a2 = fma2(v1.x, E[4 * k + 2], a2);
            a3 = fma2(v1.y, E[4 * k + 3], a3);
        }
        float sx, sy;
        unpack2(add2(add2(a0, a1), add2(a2, a3)), sx, sy);
        const float s = sx + sy;

        if (mk) { q = s * cf; Z += C; }
        qbuf[cbf][j] = q;                 // shortest chain to the next barrier

        // cheap uniform normalizer update: n = ilogb(q_0), C' = em_0 + n*ln2
        if (tid == 0) {
            const int n = (int)((__float_as_uint(q) >> 23)) - 127;
            csm[cbf] = fmaf((float)n, LN2, em_n);
        }
    }

    // out[b] = Z + ln( sum_j q_j * exp(end_j) )
    float v = q * fend;
#pragma unroll
    for (int o = 16; o; o >>= 1) v += __shfl_xor_sync(0xffffffffu, v, o);
    if (l == 0) red[w] = v;
    __syncthreads();
    if (tid == 0) out[b] = Z + __logf(red[0] + red[1]);
}

extern "C" void kernel_launch(void* const* d_in, const int* in_sizes, int n_in,
                              void* d_out, int out_size) {
    const float* emissions = (const float*)d_in[0];
    const int*   msk       = (const int*)d_in[1];
    const float* trans     = (const float*)d_in[2];
    const float* startt    = (const float*)d_in[3];
    const float* endt      = (const float*)d_in[4];
    crf_fwd_kernel<<<NB, NL>>>(emissions, msk, trans, startt, endt, (float*)d_out);
}

// round 6
// speedup vs baseline: 1.0467x; 1.0172x over previous
#include <cuda_runtime.h>

typedef unsigned long long u64;

#define NB 1024
#define SL 512
#define NL 64

__device__ __forceinline__ u64 fma2(u64 a, u64 b, u64 c) {
    u64 d;
    asm("fma.rn.f32x2 %0, %1, %2, %3;" : "=l"(d) : "l"(a), "l"(b), "l"(c));
    return d;
}
__device__ __forceinline__ u64 add2(u64 a, u64 b) {
    u64 d;
    asm("add.rn.f32x2 %0, %1, %2;" : "=l"(d) : "l"(a), "l"(b));
    return d;
}
__device__ __forceinline__ u64 pack2(float lo, float hi) {
    u64 d;
    asm("mov.b64 %0, {%1, %2};" : "=l"(d) : "f"(lo), "f"(hi));
    return d;
}
__device__ __forceinline__ void unpack2(u64 a, float& lo, float& hi) {
    asm("mov.b64 {%0, %1}, %2;" : "=f"(lo), "=f"(hi) : "l"(a));
}

// One 64-thread block = one batch. Thread j owns column j (full matvec:
// 16 LDS.128 broadcast + 32 fma2). ONE __syncthreads per step.
//
// Multiplicative recurrence, exact for any scalar normalizer C:
//   s_j = sum_i q_i E_ij ;  q'_j = s_j * exp(em_j - C) ;  Z += C
// C_{t+1} = em_0^{t+1} + n*ln2, n = exponent(q_0): pure ALU, no log in the
// hot loop. Mask handling is 100% BRANCHLESS (selects only) — multi-statement
// if(mk){} cost ~BSSY/BSYNC per step on every thread in R2-R5 and was the
// regression source vs R1.
__global__ __launch_bounds__(64) void crf_fwd_kernel(
    const float* __restrict__ emissions,
    const int*   __restrict__ mask,
    const float* __restrict__ trans,
    const float* __restrict__ startt,
    const float* __restrict__ endt,
    float* __restrict__ out)
{
    __shared__ __align__(16) float qbuf[2][NL];
    __shared__ float csm[2];
    __shared__ float red[2];

    const int tid = threadIdx.x;
    const int w   = tid >> 5;
    const int l   = tid & 31;
    const int b   = blockIdx.x;
    const size_t ebase = (size_t)b * SL * NL;
    const int j = tid;

    // E column j, packed over adjacent row pairs (matches q smem layout).
    u64 E[32];
#pragma unroll
    for (int m = 0; m < 32; m++) {
        E[m] = pack2(__expf(trans[(2 * m) * NL + j]),
                     __expf(trans[(2 * m + 1) * NL + j]));
    }
    const float fend = __expf(endt[j]);
    const float LN2 = 0.6931471805599453f;

    // t = 0: normalize by score_0 -> q_0 = 1 exactly.
    float sc = startt[j] + emissions[ebase + j];
    if (tid == 0) red[0] = sc;
    __syncthreads();
    const float z0 = red[0];
    float q = __expf(sc - z0);
    float Z = z0;
    qbuf[0][j] = q;

    // prefetch t = 1
    float em_n = emissions[ebase + NL + j];
    int   mk_n = mask[b * SL + 1];
    if (tid == 0) csm[0] = em_n;          // C_1 = em_0^1 + 0*ln2 (q_0 = 1)

#pragma unroll 2
    for (int t = 1; t < SL; t++) {
        __syncthreads();                  // publishes qbuf[pb], csm[pb]
        const int pb  = (t - 1) & 1;
        const int cbf = t & 1;
        const float C  = csm[pb];
        const float em = em_n;
        const int   mk = mk_n;

        int tn = t + 1; if (tn >= SL) tn = SL - 1;
        em_n = emissions[ebase + (size_t)tn * NL + j];
        mk_n = mask[b * SL + tn];

        // hidden under the LDS + FMA tree
        const float cf = __expf(em - C);

        // full matvec: s_j = sum_i q_i * E_ij
        const ulonglong2* qp = (const ulonglong2*)qbuf[pb];
        u64 a0 = 0, a1 = 0, a2 = 0, a3 = 0;
#pragma unroll
        for (int k = 0; k < 8; k++) {
            ulonglong2 v0 = qp[2 * k];
            ulonglong2 v1 = qp[2 * k + 1];
            a0 = fma2(v0.x, E[4 * k + 0], a0);
            a1 = fma2(v0.y, E[4 * k + 1], a1);
            a2 = fma2(v1.x, E[4 * k + 2], a2);
            a3 = fma2(v1.y, E[4 * k + 3], a3);
        }
        float sx, sy;
        unpack2(add2(add2(a0, a1), add2(a2, a3)), sx, sy);
        const float s = sx + sy;

        // BRANCHLESS mask: selects only, no BSSY.
        const float qn = s * cf;
        const float Zp = Z + C;
        q = mk ? qn : q;
        Z = mk ? Zp : Z;
        qbuf[cbf][j] = q;                 // shortest chain to the next barrier

        // uniform normalizer compute (all threads), single guarded STS.
        const int   n  = (int)(__float_as_uint(q) >> 23) - 127;
        const float Cn = fmaf((float)n, LN2, em_n);
        if (tid == 0) csm[cbf] = Cn;
    }

    // out[b] = Z + ln( sum_j q_j * exp(end_j) )
    float v = q * fend;
#pragma unroll
    for (int o = 16; o; o >>= 1) v += __shfl_xor_sync(0xffffffffu, v, o);
    if (l == 0) red[w] = v;
    __syncthreads();
    if (tid == 0) out[b] = Z + __logf(red[0] + red[1]);
}

extern "C" void kernel_launch(void* const* d_in, const int* in_sizes, int n_in,
                              void* d_out, int out_size) {
    const float* emissions = (const float*)d_in[0];
    const int*   msk       = (const int*)d_in[1];
    const float* trans     = (const float*)d_in[2];
    const float* startt    = (const float*)d_in[3];
    const float* endt      = (const float*)d_in[4];
    crf_fwd_kernel<<<NB, NL>>>(emissions, msk, trans, startt, endt, (float*)d_out);
}

// round 7
// speedup vs baseline: 1.4822x; 1.4161x over previous
#include <cuda_runtime.h>

typedef unsigned long long u64;

#define NB 1024
#define SL 512
#define NL 64

__device__ __forceinline__ u64 fma2(u64 a, u64 b, u64 c) {
    u64 d;
    asm("fma.rn.f32x2 %0, %1, %2, %3;" : "=l"(d) : "l"(a), "l"(b), "l"(c));
    return d;
}
__device__ __forceinline__ u64 add2(u64 a, u64 b) {
    u64 d;
    asm("add.rn.f32x2 %0, %1, %2;" : "=l"(d) : "l"(a), "l"(b));
    return d;
}
__device__ __forceinline__ u64 pack2(float lo, float hi) {
    u64 d;
    asm("mov.b64 %0, {%1, %2};" : "=l"(d) : "f"(lo), "f"(hi));
    return d;
}
__device__ __forceinline__ void unpack2(u64 a, float& lo, float& hi) {
    asm("mov.b64 {%0, %1}, %2;" : "=f"(lo), "=f"(hi) : "l"(a));
}

// 64-thread CTA = TWO independent batches: warp w owns batch 2*blockIdx+w.
// Lane l owns columns (2l, 2l+1): 16 LDS.128 per BATCH-step (half of R1's 32
// — L1/LDS was the binding pipe at 62%), 64 fma2 per warp-step.
// No __syncthreads; per-warp __syncwarp only (private 2x256B qbuf per warp).
//
// Multiplicative recurrence (exact for any scalar C):
//   s_j = sum_i q_i E_ij ; q'_j = s_j * exp(em_j - C) ; Z += C
// C_{t+1} = em_0^{t+1} + n*ln2, n = exponent(q_0) — pure ALU, carried in a
// register on lane 0 and broadcast with one __shfl. Mask via selects only.
__global__ __launch_bounds__(64) void crf_fwd_kernel(
    const float* __restrict__ emissions,
    const int*   __restrict__ mask,
    const float* __restrict__ trans,
    const float* __restrict__ startt,
    const float* __restrict__ endt,
    float* __restrict__ out)
{
    __shared__ __align__(16) float qbuf[2][2][NL];   // [warp][buf][label]

    const int tid = threadIdx.x;
    const int w   = tid >> 5;
    const int l   = tid & 31;
    const int b   = blockIdx.x * 2 + w;
    const size_t ebase = (size_t)b * SL * NL;
    const int ca = 2 * l;
    const int cb = 2 * l + 1;
    const unsigned FULL = 0xffffffffu;

    // E columns ca/cb, packed over adjacent row pairs (rows 2m, 2m+1) to
    // match the natural-order q layout read as ulonglong2.
    u64 Ea[32], Eb[32];
#pragma unroll
    for (int m = 0; m < 32; m++) {
        Ea[m] = pack2(__expf(trans[(2 * m) * NL + ca]),
                      __expf(trans[(2 * m + 1) * NL + ca]));
        Eb[m] = pack2(__expf(trans[(2 * m) * NL + cb]),
                      __expf(trans[(2 * m + 1) * NL + cb]));
    }
    const float fend_a = __expf(endt[ca]);
    const float fend_b = __expf(endt[cb]);
    const float LN2 = 0.6931471805599453f;

    // t = 0: normalize by score of label 0 (lane 0's sc_a) -> q_0 = 1.
    float2 e0 = *(const float2*)&emissions[ebase + ca];
    float sc_a = startt[ca] + e0.x;
    float sc_b = startt[cb] + e0.y;
    const float z0 = __shfl_sync(FULL, sc_a, 0);
    float qa = __expf(sc_a - z0);
    float qb = __expf(sc_b - z0);
    float Z = z0;
    *(float2*)&qbuf[w][0][ca] = make_float2(qa, qb);

    // prefetch t = 1
    float2 em_n = *(const float2*)&emissions[ebase + NL + ca];
    int    mk_n = mask[b * SL + 1];
    float  Cn = em_n.x;                 // lane 0: C_1 = em_0^1 + 0*ln2

#pragma unroll 2
    for (int t = 1; t < SL; t++) {
        __syncwarp(FULL);               // publishes qbuf[w][pb]
        const int pb  = (t - 1) & 1;
        const int cbf = t & 1;
        const float C   = __shfl_sync(FULL, Cn, 0);
        const float ema = em_n.x, emb = em_n.y;
        const int   mk  = mk_n;

        const int tn = (t + 1 < SL) ? t + 1 : SL - 1;
        em_n = *(const float2*)&emissions[ebase + (size_t)tn * NL + ca];
        mk_n = mask[b * SL + tn];

        // hidden under the LDS + FMA tree
        const float cfa = __expf(ema - C);
        const float cfb = __expf(emb - C);

        // full matvec for both owned columns
        const ulonglong2* qp = (const ulonglong2*)qbuf[w][pb];
        u64 a0 = 0, a1 = 0, c0 = 0, c1 = 0;
#pragma unroll
        for (int k = 0; k < 8; k++) {
            ulonglong2 v0 = qp[2 * k];
            ulonglong2 v1 = qp[2 * k + 1];
            a0 = fma2(v0.x, Ea[4 * k + 0], a0);  c0 = fma2(v0.x, Eb[4 * k + 0], c0);
            a1 = fma2(v0.y, Ea[4 * k + 1], a1);  c1 = fma2(v0.y, Eb[4 * k + 1], c1);
            a0 = fma2(v1.x, Ea[4 * k + 2], a0);  c0 = fma2(v1.x, Eb[4 * k + 2], c0);
            a1 = fma2(v1.y, Ea[4 * k + 3], a1);  c1 = fma2(v1.y, Eb[4 * k + 3], c1);
        }
        float xa, ya, xb, yb;
        unpack2(add2(a0, a1), xa, ya);
        unpack2(add2(c0, c1), xb, yb);
        const float sa = xa + ya;
        const float sb = xb + yb;

        // branchless mask
        const float qna = sa * cfa;
        const float qnb = sb * cfb;
        const float Zp  = Z + C;
        qa = mk ? qna : qa;
        qb = mk ? qnb : qb;
        Z  = mk ? Zp  : Z;
        *(float2*)&qbuf[w][cbf][ca] = make_float2(qa, qb);

        // next normalizer (valid on lane 0, broadcast next iter)
        const int n = (int)(__float_as_uint(qa) >> 23) - 127;
        Cn = fmaf((float)n, LN2, em_n.x);
    }

    // out[b] = Z + ln( sum_j q_j * exp(end_j) )
    float v = qa * fend_a + qb * fend_b;
#pragma unroll
    for (int o = 16; o; o >>= 1) v += __shfl_xor_sync(FULL, v, o);
    if (l == 0) out[b] = Z + __logf(v);
}

extern "C" void kernel_launch(void* const* d_in, const int* in_sizes, int n_in,
                              void* d_out, int out_size) {
    const float* emissions = (const float*)d_in[0];
    const int*   msk       = (const int*)d_in[1];
    const float* trans     = (const float*)d_in[2];
    const float* startt    = (const float*)d_in[3];
    const float* endt      = (const float*)d_in[4];
    crf_fwd_kernel<<<NB / 2, 64>>>(emissions, msk, trans, startt, endt, (float*)d_out);
}